// round 6
// baseline (speedup 1.0000x reference)
#include <cuda_runtime.h>
#include <cuda_bf16.h>

#define N_NODES_MAX 100000
#define IN_CH 128
#define HID 64
#define N_CLASSES 16
#define N_GRAPHS 64

// Scratch (device globals; no allocation allowed). 256B-aligned: the scatter
// path uses float4 loads and red.global.add.v4.f32, which need 16B alignment.
__device__ __align__(256) float g_dis[N_NODES_MAX];                 // deg -> rsqrt(deg)
__device__ __align__(256) float g_bufA[(size_t)N_NODES_MAX * HID];  // 25.6 MB
__device__ __align__(256) float g_bufB[(size_t)N_NODES_MAX * HID];  // 25.6 MB
__device__ __align__(256) float g_pool[N_GRAPHS * HID];
__device__ __align__(256) float g_cnt[N_GRAPHS];

__device__ __forceinline__ void dot4(float& ac, const float4& a, const float4& b) {
    ac = fmaf(a.x, b.x, ac);
    ac = fmaf(a.y, b.y, ac);
    ac = fmaf(a.z, b.z, ac);
    ac = fmaf(a.w, b.w, ac);
}

// ---------------- degree ----------------
__global__ void k_deg_init(int N) {
    int i = blockIdx.x * blockDim.x + threadIdx.x;
    if (i < N) g_dis[i] = 1.0f;  // self-loop weight
}

// NOTE: edge_index / batch are int32 on the wire (JAX x64 disabled).
__global__ void k_deg_edge(const int* __restrict__ ei,
                           const float* __restrict__ ew, int E) {
    int e = blockIdx.x * blockDim.x + threadIdx.x;
    if (e < E) atomicAdd(&g_dis[ei[E + e]], ew[e]);
}

__global__ void k_deg_rsqrt(int N) {
    int i = blockIdx.x * blockDim.x + threadIdx.x;
    if (i < N) g_dis[i] = rsqrtf(g_dis[i]);
}

// ---------------- GEMM: out = (X @ W) * dis[row], written to BOTH buffers ----------------
// X: [N, K] row-major, W: [K, 64] row-major. 64-row tile per block, 256 threads.
// Thread computes 4 rows (rr*4+i) x 4 cols (cc + 16*j).
template <int K>
__global__ __launch_bounds__(256) void k_gemm(const float* Xext, const float* __restrict__ W, int N) {
    const int S = 68;  // padded smem row stride (floats)
    __shared__ float Xs[64 * S];
    __shared__ float Ws[64 * S];  // transposed: Ws[c][k]

    const float* X = Xext ? Xext : g_bufA;
    int t = threadIdx.x;
    int rowbase = blockIdx.x * 64;
    int cc = t & 15;
    int rr = t >> 4;

    float acc[4][4] = {};

    for (int kc = 0; kc < K; kc += 64) {
        // load X tile (64 rows x 64 k) as float4, zero-pad OOB rows
        for (int f4 = t; f4 < 1024; f4 += 256) {
            int r = f4 >> 4;
            int kq = (f4 & 15) << 2;
            int row = rowbase + r;
            float4 v = make_float4(0.f, 0.f, 0.f, 0.f);
            if (row < N) v = *(const float4*)(X + (size_t)row * K + kc + kq);
            *(float4*)(Xs + r * S + kq) = v;
        }
        // load W chunk transposed
        for (int f = t; f < 4096; f += 256) {
            int kl = f >> 6;
            int c = f & 63;
            Ws[c * S + kl] = W[(size_t)(kc + kl) * 64 + c];
        }
        __syncthreads();

#pragma unroll
        for (int kl = 0; kl < 64; kl += 4) {
            float4 a0 = *(const float4*)(Xs + (rr * 4 + 0) * S + kl);
            float4 a1 = *(const float4*)(Xs + (rr * 4 + 1) * S + kl);
            float4 a2 = *(const float4*)(Xs + (rr * 4 + 2) * S + kl);
            float4 a3 = *(const float4*)(Xs + (rr * 4 + 3) * S + kl);
            float4 w0 = *(const float4*)(Ws + (cc + 0) * S + kl);
            float4 w1 = *(const float4*)(Ws + (cc + 16) * S + kl);
            float4 w2 = *(const float4*)(Ws + (cc + 32) * S + kl);
            float4 w3 = *(const float4*)(Ws + (cc + 48) * S + kl);
            dot4(acc[0][0], a0, w0); dot4(acc[0][1], a0, w1); dot4(acc[0][2], a0, w2); dot4(acc[0][3], a0, w3);
            dot4(acc[1][0], a1, w0); dot4(acc[1][1], a1, w1); dot4(acc[1][2], a1, w2); dot4(acc[1][3], a1, w3);
            dot4(acc[2][0], a2, w0); dot4(acc[2][1], a2, w1); dot4(acc[2][2], a2, w2); dot4(acc[2][3], a2, w3);
            dot4(acc[3][0], a3, w0); dot4(acc[3][1], a3, w1); dot4(acc[3][2], a3, w2); dot4(acc[3][3], a3, w3);
        }
        __syncthreads();
    }

    // epilogue: scale by dis[row], write to both buffers (acc-init = self-loop msg)
#pragma unroll
    for (int i = 0; i < 4; i++) {
        int row = rowbase + rr * 4 + i;
        if (row < N) {
            float ds = g_dis[row];
#pragma unroll
            for (int j = 0; j < 4; j++) {
                int c = cc + 16 * j;
                float v = acc[i][j] * ds;
                g_bufA[(size_t)row * HID + c] = v;
                g_bufB[(size_t)row * HID + c] = v;
            }
        }
    }
}

// ---------------- edge scatter: acc[dst] += ew * g[src] ----------------
// 16 threads per edge, float4 per lane, vector reduction.
// dir==0: read bufA, acc into bufB.  dir==1: read bufB, acc into bufA.
__global__ __launch_bounds__(256) void k_scatter(const int* __restrict__ ei,
                                                 const float* __restrict__ ew,
                                                 int E, int dir) {
    int gid = blockIdx.x * blockDim.x + threadIdx.x;
    int e = gid >> 4;
    if (e >= E) return;
    int lane = gid & 15;

    const float* g = dir ? g_bufB : g_bufA;
    float* acc = dir ? g_bufA : g_bufB;

    int s = ei[e];
    int d = ei[E + e];
    float w = __ldg(ew + e);

    float4 v = *(const float4*)(g + (size_t)s * HID + lane * 4);
    float* p = acc + (size_t)d * HID + lane * 4;
    unsigned long long gp = __cvta_generic_to_global(p);
    asm volatile("red.global.add.v4.f32 [%0], {%1,%2,%3,%4};"
                 :: "l"(gp), "f"(v.x * w), "f"(v.y * w), "f"(v.z * w), "f"(v.w * w)
                 : "memory");
}

// ---------------- bias + relu + dis[dst] scale ----------------
// dir==0: read bufB (acc), write bufA.  dir==1: read bufA, write bufB.
__global__ void k_bias_relu(const float* __restrict__ b, int N, int dir) {
    int idx = blockIdx.x * blockDim.x + threadIdx.x;
    if (idx >= N * HID) return;
    int i = idx >> 6;
    int c = idx & 63;
    const float* src = dir ? g_bufA : g_bufB;
    float* dst = dir ? g_bufB : g_bufA;
    float v = g_dis[i] * src[idx] + b[c];
    dst[idx] = v > 0.f ? v : 0.f;
}

// ---------------- pooling ----------------
__global__ void k_pool_zero() {
    int t = blockIdx.x * blockDim.x + threadIdx.x;
    if (t < N_GRAPHS * HID) g_pool[t] = 0.f;
    if (t < N_GRAPHS) g_cnt[t] = 0.f;
}

#define POOL_CHUNK 2048
// Reads bufB (H2). batch is sorted -> running-sum per thread, flush on segment change.
__global__ __launch_bounds__(256) void k_pool(const int* __restrict__ batch, int N) {
    int base = blockIdx.x * POOL_CHUNK;
    int c = threadIdx.x & 63;
    int r0 = threadIdx.x >> 6;  // 0..3
    int end = base + POOL_CHUNK;
    if (end > N) end = N;

    float s = 0.f, n = 0.f;
    int cur = -1;
    for (int i = base + r0; i < end; i += 4) {
        int gi = batch[i];
        if (gi != cur) {
            if (cur >= 0) {
                atomicAdd(g_pool + cur * 64 + c, s);
                if (c == 0) atomicAdd(g_cnt + cur, n);
            }
            cur = gi; s = 0.f; n = 0.f;
        }
        s += g_bufB[(size_t)i * HID + c];
        n += 1.f;
    }
    if (cur >= 0) {
        atomicAdd(g_pool + cur * 64 + c, s);
        if (c == 0) atomicAdd(g_cnt + cur, n);
    }
}

// ---------------- head: out[g][j] = (pool[g]/cnt[g]) @ Wl + bl ----------------
__global__ void k_head(const float* __restrict__ Wl, const float* __restrict__ bl,
                       float* __restrict__ out) {
    int t = threadIdx.x;
    if (t >= N_GRAPHS * N_CLASSES) return;
    int g = t >> 4;
    int j = t & 15;
    float inv = 1.f / fmaxf(g_cnt[g], 1.f);
    float a = bl[j];
#pragma unroll
    for (int c = 0; c < 64; c++)
        a = fmaf(g_pool[g * 64 + c] * inv, Wl[c * 16 + j], a);
    out[t] = a;
}

// ---------------- launch ----------------
extern "C" void kernel_launch(void* const* d_in, const int* in_sizes, int n_in,
                              void* d_out, int out_size) {
    const float* x = (const float*)d_in[0];
    const int* ei = (const int*)d_in[1];      // int32 (JAX x64 disabled)
    const float* ew = (const float*)d_in[2];
    const int* batch = (const int*)d_in[3];   // int32
    const float* W1 = (const float*)d_in[4];
    const float* b1 = (const float*)d_in[5];
    const float* W2 = (const float*)d_in[6];
    const float* b2 = (const float*)d_in[7];
    const float* Wl = (const float*)d_in[8];
    const float* bl = (const float*)d_in[9];
    float* out = (float*)d_out;

    int N = in_sizes[0] / IN_CH;   // 100000
    int E = in_sizes[2];           // 1600000

    int tb = 256;
    // degree + rsqrt
    k_deg_init<<<(N + tb - 1) / tb, tb>>>(N);
    k_deg_edge<<<(E + tb - 1) / tb, tb>>>(ei, ew, E);
    k_deg_rsqrt<<<(N + tb - 1) / tb, tb>>>(N);

    int gemm_blocks = (N + 63) / 64;
    long long scat_threads = (long long)E * 16;
    int scat_blocks = (int)((scat_threads + tb - 1) / tb);
    int ew_blocks = (N * HID + tb - 1) / tb;

    // layer 1
    k_gemm<IN_CH><<<gemm_blocks, tb>>>(x, W1, N);          // g1 -> A and B
    k_scatter<<<scat_blocks, tb>>>(ei, ew, E, 0);          // B += ew * A[src]
    k_bias_relu<<<ew_blocks, tb>>>(b1, N, 0);              // A = relu(dis*B + b1)

    // layer 2
    k_gemm<HID><<<gemm_blocks, tb>>>(nullptr, W2, N);      // g2 = A@W2*dis -> A and B
    k_scatter<<<scat_blocks, tb>>>(ei, ew, E, 1);          // A += ew * B[src]
    k_bias_relu<<<ew_blocks, tb>>>(b2, N, 1);              // B = relu(dis*A + b2)

    // pooling + head
    k_pool_zero<<<16, tb>>>();
    k_pool<<<(N + POOL_CHUNK - 1) / POOL_CHUNK, tb>>>(batch, N);
    k_head<<<1, 1024>>>(Wl, bl, out);
}

// round 8
// speedup vs baseline: 1.2454x; 1.2454x over previous
#include <cuda_runtime.h>
#include <cuda_bf16.h>

#define N_NODES_MAX 100000
#define E_MAX 1600000
#define IN_CH 128
#define HID 64
#define N_CLASSES 16
#define N_GRAPHS 64

// Scratch (device globals; no allocation allowed).
__device__ __align__(256) float g_dis[N_NODES_MAX];                 // deg -> rsqrt(deg)
__device__ __align__(256) float g_bufA[(size_t)N_NODES_MAX * HID];  // 25.6 MB (gemm out)
__device__ __align__(256) float g_bufB[(size_t)N_NODES_MAX * HID];  // 25.6 MB (layer out)
__device__ __align__(256) float g_pool[N_GRAPHS * HID];
__device__ __align__(256) float g_cnt[N_GRAPHS];
// CSR by destination
__device__ __align__(256) int   g_cnt_i[N_NODES_MAX];
__device__ __align__(256) int   g_rowtmp[N_NODES_MAX];
__device__ __align__(256) int   g_rowptr[N_NODES_MAX + 1];
__device__ __align__(256) int   g_fill[N_NODES_MAX];
__device__ __align__(256) int   g_bsums[128];
__device__ __align__(256) int   g_bsums_ex[128];
__device__ __align__(256) int2  g_edge[E_MAX];                      // {src, bits(w)}

__device__ __forceinline__ void dot4(float& ac, const float4& a, const float4& b) {
    ac = fmaf(a.x, b.x, ac);
    ac = fmaf(a.y, b.y, ac);
    ac = fmaf(a.z, b.z, ac);
    ac = fmaf(a.w, b.w, ac);
}

// ---------------- init: deg=1 (self loop), counts=0 ----------------
__global__ void k_init(int N) {
    int i = blockIdx.x * blockDim.x + threadIdx.x;
    if (i < N) { g_dis[i] = 1.0f; g_cnt_i[i] = 0; }
}

// ---------------- per-edge: count + weighted degree ----------------
__global__ void k_count_deg(const int* __restrict__ ei,
                            const float* __restrict__ ew, int E) {
    int e = blockIdx.x * blockDim.x + threadIdx.x;
    if (e < E) {
        int d = ei[E + e];
        atomicAdd(&g_cnt_i[d], 1);
        atomicAdd(&g_dis[d], ew[e]);
    }
}

// ---------------- prefix scan (3 kernels) ----------------
__global__ __launch_bounds__(1024) void k_scan1(int N) {
    __shared__ int sh[1024];
    int i = blockIdx.x * 1024 + threadIdx.x;
    int v = (i < N) ? g_cnt_i[i] : 0;
    sh[threadIdx.x] = v;
    __syncthreads();
    for (int off = 1; off < 1024; off <<= 1) {
        int t = (threadIdx.x >= off) ? sh[threadIdx.x - off] : 0;
        __syncthreads();
        sh[threadIdx.x] += t;
        __syncthreads();
    }
    if (i < N) g_rowtmp[i] = sh[threadIdx.x] - v;  // exclusive
    if (threadIdx.x == 1023) g_bsums[blockIdx.x] = sh[1023];
}

__global__ void k_scan2(int nb) {
    __shared__ int sh[128];
    int t = threadIdx.x;
    sh[t] = (t < nb) ? g_bsums[t] : 0;
    __syncthreads();
    if (t == 0) {
        int run = 0;
        for (int k = 0; k < nb; k++) { int c = sh[k]; sh[k] = run; run += c; }
    }
    __syncthreads();
    if (t < nb) g_bsums_ex[t] = sh[t];
}

// rowptr = rowtmp + block offset; also fill cursor init and dis=rsqrt(deg)
__global__ void k_scan3(int N, int E) {
    int i = blockIdx.x * blockDim.x + threadIdx.x;
    if (i < N) {
        int rp = g_rowtmp[i] + g_bsums_ex[i >> 10];
        g_rowptr[i] = rp;
        g_fill[i] = rp;
        g_dis[i] = rsqrtf(g_dis[i]);
    }
    if (i == 0) g_rowptr[N] = E;
}

// ---------------- fill CSR: edge -> slot ----------------
__global__ void k_fill(const int* __restrict__ ei,
                       const float* __restrict__ ew, int E) {
    int e = blockIdx.x * blockDim.x + threadIdx.x;
    if (e < E) {
        int d = ei[E + e];
        int slot = atomicAdd(&g_fill[d], 1);
        g_edge[slot] = make_int2(ei[e], __float_as_int(ew[e]));
    }
}

// ---------------- GEMM: bufA = (X @ W) * dis[row] ----------------
// src==0: X = Xext (input features). src==1: X = g_bufB (prev layer out).
template <int K>
__global__ __launch_bounds__(256) void k_gemm(const float* Xext, const float* __restrict__ W,
                                              int N, int src) {
    const int S = 68;  // padded smem row stride (floats)
    __shared__ float Xs[64 * S];
    __shared__ float Ws[64 * S];  // transposed: Ws[c][k]

    const float* X = (src == 0) ? Xext : g_bufB;
    int t = threadIdx.x;
    int rowbase = blockIdx.x * 64;
    int cc = t & 15;
    int rr = t >> 4;

    float acc[4][4] = {};

    for (int kc = 0; kc < K; kc += 64) {
        for (int f4 = t; f4 < 1024; f4 += 256) {
            int r = f4 >> 4;
            int kq = (f4 & 15) << 2;
            int row = rowbase + r;
            float4 v = make_float4(0.f, 0.f, 0.f, 0.f);
            if (row < N) v = *(const float4*)(X + (size_t)row * K + kc + kq);
            *(float4*)(Xs + r * S + kq) = v;
        }
        for (int f = t; f < 4096; f += 256) {
            int kl = f >> 6;
            int c = f & 63;
            Ws[c * S + kl] = W[(size_t)(kc + kl) * 64 + c];
        }
        __syncthreads();

#pragma unroll
        for (int kl = 0; kl < 64; kl += 4) {
            float4 a0 = *(const float4*)(Xs + (rr * 4 + 0) * S + kl);
            float4 a1 = *(const float4*)(Xs + (rr * 4 + 1) * S + kl);
            float4 a2 = *(const float4*)(Xs + (rr * 4 + 2) * S + kl);
            float4 a3 = *(const float4*)(Xs + (rr * 4 + 3) * S + kl);
            float4 w0 = *(const float4*)(Ws + (cc + 0) * S + kl);
            float4 w1 = *(const float4*)(Ws + (cc + 16) * S + kl);
            float4 w2 = *(const float4*)(Ws + (cc + 32) * S + kl);
            float4 w3 = *(const float4*)(Ws + (cc + 48) * S + kl);
            dot4(acc[0][0], a0, w0); dot4(acc[0][1], a0, w1); dot4(acc[0][2], a0, w2); dot4(acc[0][3], a0, w3);
            dot4(acc[1][0], a1, w0); dot4(acc[1][1], a1, w1); dot4(acc[1][2], a1, w2); dot4(acc[1][3], a1, w3);
            dot4(acc[2][0], a2, w0); dot4(acc[2][1], a2, w1); dot4(acc[2][2], a2, w2); dot4(acc[2][3], a2, w3);
            dot4(acc[3][0], a3, w0); dot4(acc[3][1], a3, w1); dot4(acc[3][2], a3, w2); dot4(acc[3][3], a3, w3);
        }
        __syncthreads();
    }

#pragma unroll
    for (int i = 0; i < 4; i++) {
        int row = rowbase + rr * 4 + i;
        if (row < N) {
            float ds = g_dis[row];
#pragma unroll
            for (int j = 0; j < 4; j++) {
                int c = cc + 16 * j;
                g_bufA[(size_t)row * HID + c] = acc[i][j] * ds;
            }
        }
    }
}

// ---------------- gather + dis + bias + relu (pull-mode aggregation) ----------------
// One warp per node, 32 lanes x float2. bufA -> bufB.
// acc init = g[node] (self loop, weight 1).
__global__ __launch_bounds__(256) void k_gather(const float* __restrict__ bias, int N) {
    int node = (blockIdx.x * 256 + threadIdx.x) >> 5;
    if (node >= N) return;
    int lane = threadIdx.x & 31;

    const float2* G = (const float2*)g_bufA;
    int base = node * 32 + lane;
    float2 acc = G[base];

    int k = g_rowptr[node];
    int s1 = g_rowptr[node + 1];
    for (; k + 1 < s1; k += 2) {
        int2 e0 = g_edge[k];
        int2 e1 = g_edge[k + 1];
        float2 v0 = G[e0.x * 32 + lane];
        float2 v1 = G[e1.x * 32 + lane];
        float w0 = __int_as_float(e0.y);
        float w1 = __int_as_float(e1.y);
        acc.x = fmaf(w0, v0.x, acc.x); acc.y = fmaf(w0, v0.y, acc.y);
        acc.x = fmaf(w1, v1.x, acc.x); acc.y = fmaf(w1, v1.y, acc.y);
    }
    if (k < s1) {
        int2 e0 = g_edge[k];
        float2 v0 = G[e0.x * 32 + lane];
        float w0 = __int_as_float(e0.y);
        acc.x = fmaf(w0, v0.x, acc.x); acc.y = fmaf(w0, v0.y, acc.y);
    }

    float ds = g_dis[node];
    float bx = bias[lane * 2];
    float by = bias[lane * 2 + 1];
    float ox = fmaf(ds, acc.x, bx);
    float oy = fmaf(ds, acc.y, by);
    float2 o;
    o.x = ox > 0.f ? ox : 0.f;
    o.y = oy > 0.f ? oy : 0.f;
    ((float2*)g_bufB)[base] = o;
}

// ---------------- pooling ----------------
__global__ void k_pool_zero() {
    int t = blockIdx.x * blockDim.x + threadIdx.x;
    if (t < N_GRAPHS * HID) g_pool[t] = 0.f;
    if (t < N_GRAPHS) g_cnt[t] = 0.f;
}

#define POOL_CHUNK 2048
__global__ __launch_bounds__(256) void k_pool(const int* __restrict__ batch, int N) {
    int base = blockIdx.x * POOL_CHUNK;
    int c = threadIdx.x & 63;
    int r0 = threadIdx.x >> 6;  // 0..3
    int end = base + POOL_CHUNK;
    if (end > N) end = N;

    float s = 0.f, n = 0.f;
    int cur = -1;
    for (int i = base + r0; i < end; i += 4) {
        int gi = batch[i];
        if (gi != cur) {
            if (cur >= 0) {
                atomicAdd(g_pool + cur * 64 + c, s);
                if (c == 0) atomicAdd(g_cnt + cur, n);
            }
            cur = gi; s = 0.f; n = 0.f;
        }
        s += g_bufB[(size_t)i * HID + c];
        n += 1.f;
    }
    if (cur >= 0) {
        atomicAdd(g_pool + cur * 64 + c, s);
        if (c == 0) atomicAdd(g_cnt + cur, n);
    }
}

// ---------------- head ----------------
__global__ void k_head(const float* __restrict__ Wl, const float* __restrict__ bl,
                       float* __restrict__ out) {
    int t = threadIdx.x;
    if (t >= N_GRAPHS * N_CLASSES) return;
    int g = t >> 4;
    int j = t & 15;
    float inv = 1.f / fmaxf(g_cnt[g], 1.f);
    float a = bl[j];
#pragma unroll
    for (int c = 0; c < 64; c++)
        a = fmaf(g_pool[g * 64 + c] * inv, Wl[c * 16 + j], a);
    out[t] = a;
}

// ---------------- launch ----------------
extern "C" void kernel_launch(void* const* d_in, const int* in_sizes, int n_in,
                              void* d_out, int out_size) {
    const float* x = (const float*)d_in[0];
    const int* ei = (const int*)d_in[1];      // int32 (JAX x64 disabled)
    const float* ew = (const float*)d_in[2];
    const int* batch = (const int*)d_in[3];   // int32
    const float* W1 = (const float*)d_in[4];
    const float* b1 = (const float*)d_in[5];
    const float* W2 = (const float*)d_in[6];
    const float* b2 = (const float*)d_in[7];
    const float* Wl = (const float*)d_in[8];
    const float* bl = (const float*)d_in[9];
    float* out = (float*)d_out;

    int N = in_sizes[0] / IN_CH;   // 100000
    int E = in_sizes[2];           // 1600000

    int tb = 256;
    int nblk = (N + tb - 1) / tb;
    int eblk = (E + tb - 1) / tb;
    int nb_scan = (N + 1023) / 1024;

    // ---- CSR build + degree ----
    k_init<<<nblk, tb>>>(N);
    k_count_deg<<<eblk, tb>>>(ei, ew, E);
    k_scan1<<<nb_scan, 1024>>>(N);
    k_scan2<<<1, 128>>>(nb_scan);
    k_scan3<<<nblk, tb>>>(N, E);
    k_fill<<<eblk, tb>>>(ei, ew, E);

    int gemm_blocks = (N + 63) / 64;
    int gather_blocks = (N * 32 + tb - 1) / tb;

    // layer 1
    k_gemm<IN_CH><<<gemm_blocks, tb>>>(x, W1, N, 0);   // A = (x@W1)*dis
    k_gather<<<gather_blocks, tb>>>(b1, N);            // B = relu(dis*(agg A) + b1)

    // layer 2
    k_gemm<HID><<<gemm_blocks, tb>>>(nullptr, W2, N, 1); // A = (B@W2)*dis
    k_gather<<<gather_blocks, tb>>>(b2, N);              // B = relu(dis*(agg A) + b2)

    // pooling + head
    k_pool_zero<<<16, tb>>>();
    k_pool<<<(N + POOL_CHUNK - 1) / POOL_CHUNK, tb>>>(batch, N);
    k_head<<<1, 1024>>>(Wl, bl, out);
}